// round 16
// baseline (speedup 1.0000x reference)
#include <cuda_runtime.h>
#include <cuda_fp16.h>
#include <math.h>
#include <stdint.h>

// Problem constants
#define SQ   3136
#define NH   16
#define HD   80
#define HID  1280
#define HID3 3840
#define GK   1280
#define MPAD 3200          // 25 * 128
#define SCALE_LOG2 0.16129841552f   // (1/sqrt(80)) * log2(e)

// ---------------- scratch (device globals; no allocs allowed) ----------------
__device__ __half g_qkvh[(size_t)SQ * HID3];          // fp16 qkv
__device__ __half gx_h [(size_t)MPAD * GK];
__device__ __half gw1_h[(size_t)HID3 * GK];
__device__ __half gw2_h[(size_t)HID  * GK];
__device__ __half ga_h [(size_t)MPAD * GK];
__device__ __half g_qh[(size_t)NH * SQ * HD + 8192];  // pad: last CTA reads past end
__device__ __half g_kh[(size_t)NH * SQ * HD + 8192];
__device__ __half g_vh[(size_t)NH * SQ * HD + 8192];

// ============================ PTX helpers ====================================
__device__ __forceinline__ uint32_t smem_u32(const void* p) {
    uint32_t a;
    asm("{ .reg .u64 t; cvta.to.shared.u64 t, %1; cvt.u32.u64 %0, t; }"
        : "=r"(a) : "l"(p));
    return a;
}
__device__ __forceinline__ void cp16(uint32_t dst, const void* src) {
    asm volatile("cp.async.cg.shared.global [%0], [%1], 16;" :: "r"(dst), "l"(src));
}
#define CP_COMMIT() asm volatile("cp.async.commit_group;" ::: "memory")
#define CP_WAIT(n)  asm volatile("cp.async.wait_group %0;" :: "n"(n) : "memory")

__device__ __forceinline__ void ldm_x4(uint32_t* r, uint32_t a) {
    asm volatile("ldmatrix.sync.aligned.m8n8.x4.shared.b16 {%0,%1,%2,%3}, [%4];"
        : "=r"(r[0]), "=r"(r[1]), "=r"(r[2]), "=r"(r[3]) : "r"(a));
}
__device__ __forceinline__ void ldm_x4t(uint32_t* r, uint32_t a) {
    asm volatile("ldmatrix.sync.aligned.m8n8.x4.trans.shared.b16 {%0,%1,%2,%3}, [%4];"
        : "=r"(r[0]), "=r"(r[1]), "=r"(r[2]), "=r"(r[3]) : "r"(a));
}
// fp32-accum HMMA
__device__ __forceinline__ void mma16816(float* c, const uint32_t* a, const uint32_t* b) {
    asm volatile("mma.sync.aligned.m16n8k16.row.col.f32.f16.f16.f32 "
        "{%0,%1,%2,%3}, {%4,%5,%6,%7}, {%8,%9}, {%0,%1,%2,%3};"
        : "+f"(c[0]), "+f"(c[1]), "+f"(c[2]), "+f"(c[3])
        : "r"(a[0]), "r"(a[1]), "r"(a[2]), "r"(a[3]), "r"(b[0]), "r"(b[1]));
}
// fp16-accum HMMA (C = 2 packed half2 regs; layout == PV A-fragment layout)
__device__ __forceinline__ void mma16816h(uint32_t* c, const uint32_t* a, const uint32_t* b) {
    asm volatile("mma.sync.aligned.m16n8k16.row.col.f16.f16.f16.f16 "
        "{%0,%1}, {%2,%3,%4,%5}, {%6,%7}, {%0,%1};"
        : "+r"(c[0]), "+r"(c[1])
        : "r"(a[0]), "r"(a[1]), "r"(a[2]), "r"(a[3]), "r"(b[0]), "r"(b[1]));
}
#define SW128(o) ((o) ^ (((o) >> 3) & 0x70))

// ============================================================================
// fused pack fp32 -> fp16 for three tensors (vectorized x4)
// ============================================================================
__global__ void pack3_kernel(const float4* __restrict__ s0, uint2* __restrict__ d0, size_t n0,
                             const float4* __restrict__ s1, uint2* __restrict__ d1, size_t n1,
                             const float4* __restrict__ s2, uint2* __restrict__ d2, size_t n2)
{
    const size_t total = n0 + n1 + n2;
    for (size_t i = blockIdx.x * (size_t)blockDim.x + threadIdx.x; i < total;
         i += (size_t)gridDim.x * blockDim.x) {
        const float4* s; uint2* d; size_t k;
        if (i < n0)           { s = s0; d = d0; k = i; }
        else if (i < n0 + n1) { s = s1; d = d1; k = i - n0; }
        else                  { s = s2; d = d2; k = i - n0 - n1; }
        float4 v = s[k];
        __half2 lo; lo.x = __float2half_rn(v.x); lo.y = __float2half_rn(v.y);
        __half2 hi; hi.x = __float2half_rn(v.z); hi.y = __float2half_rn(v.w);
        uint2 o; o.x = *(uint32_t*)&lo; o.y = *(uint32_t*)&hi;
        d[k] = o;
    }
}

// ============================================================================
// HGEMM NT: C[M,N] = A[M,K]@B[N,K]^T + bias (+resid). OutT = float or __half.
// 128x128 CTA, 8 warps (64x32/warp), KC=64, SW128, 3-stage cp.async.
// ============================================================================
#define HG_STAGE 32768
#define HG_SMEM  (3 * HG_STAGE)   // 98304
#define NCH (GK / 64)             // 20

template <typename OutT, bool RESID>
__global__ __launch_bounds__(256)
void hgemm_nt_kernel(OutT* __restrict__ C,
                     const __half* __restrict__ A,
                     const __half* __restrict__ B,
                     const float* __restrict__ bias,
                     const float* __restrict__ Rz,
                     int M, int N)
{
    extern __shared__ char smem[];
    const uint32_t sb = smem_u32(smem);
    const int tid = threadIdx.x, lane = tid & 31, wid = tid >> 5;
    const int wm = wid >> 2, wn = wid & 3;
    const int m0 = blockIdx.y * 128, n0 = blockIdx.x * 128;

    float c[4][4][4];
#pragma unroll
    for (int i = 0; i < 4; i++)
#pragma unroll
        for (int j = 0; j < 4; j++)
#pragma unroll
            for (int r = 0; r < 4; r++) c[i][j][r] = 0.f;

    auto issue = [&](int st, int kk) {
        const uint32_t Ab = sb + st * HG_STAGE;
#pragma unroll
        for (int i = 0; i < 4; i++) {
            int lin = tid + i * 256;
            int r = lin >> 3, seg = lin & 7;
            cp16(Ab + SW128((uint32_t)(r * 128 + seg * 16)),
                 A + (size_t)(m0 + r) * GK + kk + seg * 8);
        }
#pragma unroll
        for (int i = 0; i < 4; i++) {
            int lin = tid + i * 256;
            int r = lin >> 3, seg = lin & 7;
            cp16(Ab + 16384 + SW128((uint32_t)(r * 128 + seg * 16)),
                 B + (size_t)(n0 + r) * GK + kk + seg * 8);
        }
        CP_COMMIT();
    };

    issue(0, 0);
    issue(1, 64);
    for (int ch = 0; ch < NCH; ch++) {
        if (ch + 2 < NCH) { issue((ch + 2) % 3, (ch + 2) * 64); CP_WAIT(2); }
        else if (ch + 1 < NCH) { CP_WAIT(1); }
        else { CP_WAIT(0); }
        __syncthreads();

        const uint32_t Ab = sb + (ch % 3) * HG_STAGE;
        const uint32_t Bb = Ab + 16384;
#pragma unroll
        for (int ks = 0; ks < 4; ks++) {
            const int kk = ks * 16;
            uint32_t a[4][4];
#pragma unroll
            for (int i = 0; i < 4; i++) {
                int row = wm * 64 + i * 16 + (lane & 7) + ((lane >> 3) & 1) * 8;
                int ko  = kk + (lane >> 4) * 8;
                ldm_x4(a[i], Ab + SW128((uint32_t)(row * 128 + ko * 2)));
            }
#pragma unroll
            for (int j = 0; j < 2; j++) {
                uint32_t b4[4];
                int rowb = wn * 32 + j * 16 + (lane & 7) + (lane >> 4) * 8;
                int kob  = kk + ((lane >> 3) & 1) * 8;
                ldm_x4(b4, Bb + SW128((uint32_t)(rowb * 128 + kob * 2)));
#pragma unroll
                for (int i = 0; i < 4; i++) {
                    mma16816(c[i][2 * j],     a[i], b4);
                    mma16816(c[i][2 * j + 1], a[i], b4 + 2);
                }
            }
        }
        __syncthreads();
    }

    // epilogue
#pragma unroll
    for (int i = 0; i < 4; i++) {
        const int row = m0 + wm * 64 + i * 16 + (lane >> 2);
#pragma unroll
        for (int j = 0; j < 4; j++) {
            const int col = n0 + wn * 32 + j * 8 + (lane & 3) * 2;
            const float2 bv = *(const float2*)&bias[col];
#pragma unroll
            for (int h = 0; h < 2; h++) {
                const int rr = row + h * 8;
                if (rr >= M) continue;
                float ox = c[i][j][2 * h]     + bv.x;
                float oy = c[i][j][2 * h + 1] + bv.y;
                if (RESID) {
                    float2 rv = *(const float2*)&Rz[(size_t)rr * N + col];
                    ox += rv.x; oy += rv.y;
                }
                if (sizeof(OutT) == 2) {
                    __half2 hv; hv.x = __float2half_rn(ox); hv.y = __float2half_rn(oy);
                    *(__half2*)&((__half*)C)[(size_t)rr * N + col] = hv;
                } else {
                    *(float2*)&((float*)C)[(size_t)rr * N + col] = make_float2(ox, oy);
                }
            }
        }
    }
}

// ============================================================================
// RoPE + split, vectorized: cos/sin tables satisfy cos[d+40]==cos[d], so each
// thread handles the (d, d+40) pair for 2 consecutive d with one cos/sin load.
// q pre-scaled by SCALE*log2(e).
// ============================================================================
__global__ void rope_split_kernel(const float* __restrict__ cosb,
                                  const float* __restrict__ sinb)
{
    const int s = blockIdx.x;
    const __half2* row = (const __half2*)(g_qkvh + (size_t)s * HID3);
    for (int it = threadIdx.x; it < NH * 20; it += blockDim.x) {
        const int h = it / 20, dp = it - h * 20;    // dp: half2 index within [0,40)
        const int d = dp * 2;
        const float2 c2 = *(const float2*)&cosb[s * HD + d];
        const float2 s2 = *(const float2*)&sinb[s * HD + d];
        const int base = h * 40;                    // half2 units within 640-wide row

        __half2 qlo = row[base + dp],        qhi = row[base + 20 + dp];
        __half2 klo = row[640 + base + dp],  khi = row[640 + base + 20 + dp];
        __half2 vlo = row[1280 + base + dp], vhi = row[1280 + base + 20 + dp];

        float2 ql = __half22float2(qlo), qh2 = __half22float2(qhi);
        float2 kl = __half22float2(klo), kh2 = __half22float2(khi);

        __half2 qo_lo, qo_hi, ko_lo, ko_hi;
        qo_lo.x = __float2half_rn((ql.x * c2.x - qh2.x * s2.x) * SCALE_LOG2);
        qo_lo.y = __float2half_rn((ql.y * c2.y - qh2.y * s2.y) * SCALE_LOG2);
        qo_hi.x = __float2half_rn((qh2.x * c2.x + ql.x * s2.x) * SCALE_LOG2);
        qo_hi.y = __float2half_rn((qh2.y * c2.y + ql.y * s2.y) * SCALE_LOG2);
        ko_lo.x = __float2half_rn(kl.x * c2.x - kh2.x * s2.x);
        ko_lo.y = __float2half_rn(kl.y * c2.y - kh2.y * s2.y);
        ko_hi.x = __float2half_rn(kh2.x * c2.x + kl.x * s2.x);
        ko_hi.y = __float2half_rn(kh2.y * c2.y + kl.y * s2.y);

        const size_t ob = ((size_t)h * SQ + s) * HD + d;   // element index (even)
        *(__half2*)&g_qh[ob]      = qo_lo;
        *(__half2*)&g_qh[ob + 40] = qo_hi;
        *(__half2*)&g_kh[ob]      = ko_lo;
        *(__half2*)&g_kh[ob + 40] = ko_hi;
        *(__half2*)&g_vh[ob]      = vlo;
        *(__half2*)&g_vh[ob + 40] = vhi;
    }
}

// ============================================================================
// Flash attention v4: 8 warps, n-split. Warp w (g = w>>2, mr = w&3) handles
// q-rows mr*32..mr*32+31 x keys [g*32, g*32+32) of each 64-key tile.
// Work per warp is halved vs v3; warps/SM doubles (reg cap 128, 2 CTAs/SM).
// Q lives in a dedicated smem region, fragments re-ldmatrix'd per tile.
// Fixed-max softmax => end merge of warp pairs (w, w+4) is a plain (o,l) sum.
// grid (25, 16), 256 threads. smem: Q 22528 + 3 KV stages x 22528 = 90112.
// ============================================================================
#define FK_BYTES 11264          // 64 * 176
#define FSTAGE   22528          // K + V
#define FQBYTES  22528          // Q region: 128 * 176
#define F_SMEM   (FQBYTES + 3 * FSTAGE)   // 90112
#define NKT      (SQ / 64)      // 49

__global__ __launch_bounds__(256, 2)
void flash_mma_kernel()
{
    extern __shared__ char smem[];
    const uint32_t sb = smem_u32(smem);       // Q region
    const uint32_t stg = sb + FQBYTES;        // KV stages
    const int tid = threadIdx.x, lane = tid & 31, wid = tid >> 5;
    const int g = wid >> 2;                   // key-group 0/1
    const int mr = wid & 3;                   // row-group 0..3
    const int hh = blockIdx.y, q0 = blockIdx.x * 128;
    const __half* qh = g_qh + (size_t)hh * SQ * HD;
    const __half* kh = g_kh + (size_t)hh * SQ * HD;
    const __half* vh = g_vh + (size_t)hh * SQ * HD;

    auto issue_kv = [&](int buf, int kbase) {
        const uint32_t Kb = stg + buf * FSTAGE;
#pragma unroll
        for (int i = 0; i < 5; i++) {
            int lin = tid + i * 256;
            if (lin < 640) {
                int r = lin / 10, seg = lin % 10;
                cp16(Kb + (uint32_t)(r * 176 + seg * 16),
                     kh + (size_t)(kbase + r) * HD + seg * 8);
            } else {
                int l2 = lin - 640;
                int r = l2 / 10, seg = l2 % 10;
                cp16(Kb + FK_BYTES + (uint32_t)(r * 176 + seg * 16),
                     vh + (size_t)(kbase + r) * HD + seg * 8);
            }
        }
        CP_COMMIT();
    };

    // ---- load Q tile (128 rows x 176B) into its own region ----
#pragma unroll
    for (int i = 0; i < 5; i++) {
        int lin = tid + i * 256;
        int r = lin / 10, seg = lin % 10;
        cp16(sb + (uint32_t)(r * 176 + seg * 16),
             qh + (size_t)(q0 + r) * HD + seg * 8);
    }
    CP_COMMIT();
    issue_kv(0, 0);
    issue_kv(1, 64);

    float o[2][10][4];
#pragma unroll
    for (int h = 0; h < 2; h++)
#pragma unroll
        for (int d = 0; d < 10; d++)
#pragma unroll
            for (int r = 0; r < 4; r++) o[h][d][r] = 0.f;
    float l[2][2] = {{0.f, 0.f}, {0.f, 0.f}};
    const __half2 clampv = __floats2half2_rn(11.f, 11.f);   // p <= 2048

    for (int kt = 0; kt < NKT; kt++) {
        if (kt < NKT - 1) { CP_WAIT(1); } else { CP_WAIT(0); }
        __syncthreads();
        if (kt + 2 < NKT) issue_kv((kt + 2) % 3, (kt + 2) * 64);

        const uint32_t Kb = stg + (kt % 3) * FSTAGE;
        const uint32_t Vb = Kb + FK_BYTES;

        // S = Q @ K^T  (32 q-rows x 32 keys per warp, fp16 accum, exp2 domain)
        uint32_t c[2][4][2];
#pragma unroll
        for (int h = 0; h < 2; h++)
#pragma unroll
            for (int j = 0; j < 4; j++) { c[h][j][0] = 0u; c[h][j][1] = 0u; }

#pragma unroll
        for (int ks = 0; ks < 5; ks++) {
            uint32_t a[2][4];
#pragma unroll
            for (int h = 0; h < 2; h++) {
                int row = mr * 32 + h * 16 + (lane & 7) + ((lane >> 3) & 1) * 8;
                int ko  = ks * 16 + (lane >> 4) * 8;
                ldm_x4(a[h], sb + (uint32_t)(row * 176 + ko * 2));
            }
#pragma unroll
            for (int j2 = 0; j2 < 2; j2++) {
                uint32_t b4[4];
                int rowb = g * 32 + j2 * 16 + (lane & 7) + (lane >> 4) * 8;
                int kob  = ks * 16 + ((lane >> 3) & 1) * 8;
                ldm_x4(b4, Kb + (uint32_t)(rowb * 176 + kob * 2));
#pragma unroll
                for (int h = 0; h < 2; h++) {
                    mma16816h(c[h][2 * j2],     a[h], b4);
                    mma16816h(c[h][2 * j2 + 1], a[h], b4 + 2);
                }
            }
        }

        // p = 2^s in place; accumulate l
#pragma unroll
        for (int h = 0; h < 2; h++) {
            __half2 acc0 = __floats2half2_rn(0.f, 0.f);
            __half2 acc1 = acc0;
#pragma unroll
            for (int j = 0; j < 4; j++) {
                __half2 v0 = h2exp2(__hmin2(*(__half2*)&c[h][j][0], clampv));
                __half2 v1 = h2exp2(__hmin2(*(__half2*)&c[h][j][1], clampv));
                c[h][j][0] = *(uint32_t*)&v0;
                c[h][j][1] = *(uint32_t*)&v1;
                acc0 = __hadd2(acc0, v0);
                acc1 = __hadd2(acc1, v1);
            }
            float2 f0 = __half22float2(acc0), f1 = __half22float2(acc1);
            l[h][0] += f0.x + f0.y;
            l[h][1] += f1.x + f1.y;
        }

        // O += P @ V   (k = this warp's 32 keys)
#pragma unroll
        for (int jj = 0; jj < 2; jj++) {
#pragma unroll
            for (int d2 = 0; d2 < 5; d2++) {
                uint32_t b4[4];
                int rowv = g * 32 + jj * 16 + (lane & 7) + ((lane >> 3) & 1) * 8;
                int c16  = d2 * 2 + (lane >> 4);
                ldm_x4t(b4, Vb + (uint32_t)(rowv * 176 + c16 * 16));
#pragma unroll
                for (int h = 0; h < 2; h++) {
                    uint32_t ap[4] = {c[h][2 * jj][0], c[h][2 * jj][1],
                                      c[h][2 * jj + 1][0], c[h][2 * jj + 1][1]};
                    mma16816(o[h][2 * d2],     ap, b4);
                    mma16816(o[h][2 * d2 + 1], ap, b4 + 2);
                }
            }
        }
    }

    // ---- merge warp pairs (w, w+4): plain sums of o and l ----
    __syncthreads();               // everyone done with KV stages
    float* mo = (float*)(smem + FQBYTES);            // [80][128]
    float* ml = (float*)(smem + FQBYTES + 40960);    // [4][128]
    if (g == 1) {
        const int slot = mr * 32 + lane;
#pragma unroll
        for (int h = 0; h < 2; h++)
#pragma unroll
            for (int d = 0; d < 10; d++)
#pragma unroll
                for (int r = 0; r < 4; r++)
                    mo[((h * 10 + d) * 4 + r) * 128 + slot] = o[h][d][r];
#pragma unroll
        for (int h = 0; h < 2; h++)
#pragma unroll
            for (int gg = 0; gg < 2; gg++)
                ml[(h * 2 + gg) * 128 + slot] = l[h][gg];
    }
    __syncthreads();
    if (g == 0) {
        const int slot = mr * 32 + lane;
#pragma unroll
        for (int h = 0; h < 2; h++)
#pragma unroll
            for (int d = 0; d < 10; d++)
#pragma unroll
                for (int r = 0; r < 4; r++)
                    o[h][d][r] += mo[((h * 10 + d) * 4 + r) * 128 + slot];
#pragma unroll
        for (int h = 0; h < 2; h++)
#pragma unroll
            for (int gg = 0; gg < 2; gg++) {
                l[h][gg] += ml[(h * 2 + gg) * 128 + slot];
                l[h][gg] += __shfl_xor_sync(0xffffffffu, l[h][gg], 1);
                l[h][gg] += __shfl_xor_sync(0xffffffffu, l[h][gg], 2);
            }

        // write attn fp16 (rows >= SQ land in ga_h padding; ignored by proj)
#pragma unroll
        for (int h = 0; h < 2; h++) {
            const float il0 = 1.f / l[h][0], il1 = 1.f / l[h][1];
            const int r0 = q0 + mr * 32 + h * 16 + (lane >> 2);
#pragma unroll
            for (int d = 0; d < 10; d++) {
                const int col = hh * HD + d * 8 + (lane & 3) * 2;
                __half2 h0; h0.x = __float2half_rn(o[h][d][0] * il0);
                            h0.y = __float2half_rn(o[h][d][1] * il0);
                *(__half2*)&ga_h[(size_t)r0 * GK + col] = h0;
                __half2 h1; h1.x = __float2half_rn(o[h][d][2] * il1);
                            h1.y = __float2half_rn(o[h][d][3] * il1);
                *(__half2*)&ga_h[(size_t)(r0 + 8) * GK + col] = h1;
            }
        }
    }
}

// ============================================================================
// launch
// ============================================================================
extern "C" void kernel_launch(void* const* d_in, const int* in_sizes, int n_in,
                              void* d_out, int out_size)
{
    const float* hidden  = (const float*)d_in[0];
    const float* x_norm  = (const float*)d_in[1];
    const float* qkv_w   = (const float*)d_in[2];
    const float* qkv_b   = (const float*)d_in[3];
    const float* proj_w  = (const float*)d_in[4];
    const float* proj_b  = (const float*)d_in[5];
    const float* cosb    = (const float*)d_in[6];
    const float* sinb    = (const float*)d_in[7];
    float* out = (float*)d_out;

    __half *qkvh, *xh, *w1h, *w2h, *ah;
    cudaGetSymbolAddress((void**)&qkvh, g_qkvh);
    cudaGetSymbolAddress((void**)&xh,  gx_h);
    cudaGetSymbolAddress((void**)&w1h, gw1_h);
    cudaGetSymbolAddress((void**)&w2h, gw2_h);
    cudaGetSymbolAddress((void**)&ah,  ga_h);

    cudaFuncSetAttribute(hgemm_nt_kernel<__half, false>,
                         cudaFuncAttributeMaxDynamicSharedMemorySize, HG_SMEM);
    cudaFuncSetAttribute(hgemm_nt_kernel<float, true>,
                         cudaFuncAttributeMaxDynamicSharedMemorySize, HG_SMEM);
    cudaFuncSetAttribute(flash_mma_kernel,
                         cudaFuncAttributeMaxDynamicSharedMemorySize, F_SMEM);

    // 0. pack all three fp32 inputs to fp16 (one fused kernel, float4 lanes)
    pack3_kernel<<<1184, 256>>>(
        (const float4*)x_norm, (uint2*)xh,  (size_t)SQ * GK / 4,
        (const float4*)qkv_w,  (uint2*)w1h, (size_t)HID3 * GK / 4,
        (const float4*)proj_w, (uint2*)w2h, (size_t)HID * GK / 4);

    // 1. qkv = x_norm @ qkv_w^T + qkv_b (fp16 out)
    {
        dim3 grid(HID3 / 128, MPAD / 128);
        hgemm_nt_kernel<__half, false><<<grid, 256, HG_SMEM>>>(
            qkvh, xh, w1h, qkv_b, nullptr, SQ, HID3);
    }
    // 2. rope + split to fp16 [H,S,D] (q pre-scaled into exp2 domain)
    rope_split_kernel<<<SQ, 256>>>(cosb, sinb);

    // 3. flash attention v4 (n-split, 8 warps)
    {
        dim3 grid((SQ + 127) / 128, NH);
        flash_mma_kernel<<<grid, 256, F_SMEM>>>();
    }
    // 4. out = hidden + attn @ proj_w^T + proj_b
    {
        dim3 grid(HID / 128, MPAD / 128);
        hgemm_nt_kernel<float, true><<<grid, 256, HG_SMEM>>>(
            out, ah, w2h, proj_b, hidden, SQ, HID);
    }
}

// round 17
// speedup vs baseline: 1.0547x; 1.0547x over previous
#include <cuda_runtime.h>
#include <cuda_fp16.h>
#include <math.h>
#include <stdint.h>

// Problem constants
#define SQ   3136
#define NH   16
#define HD   80
#define HID  1280
#define HID3 3840
#define GK   1280
#define MPAD 3200          // 25 * 128
#define SCALE_LOG2 0.16129841552f   // (1/sqrt(80)) * log2(e)

// ---------------- scratch (device globals; no allocs allowed) ----------------
__device__ __half g_qkvh[(size_t)SQ * HID3];          // fp16 qkv
__device__ __half gx_h [(size_t)MPAD * GK];
__device__ __half gw1_h[(size_t)HID3 * GK];
__device__ __half gw2_h[(size_t)HID  * GK];
__device__ __half ga_h [(size_t)MPAD * GK];
__device__ __half g_qh[(size_t)NH * SQ * HD + 8192];  // pad: last CTA reads past end
__device__ __half g_kh[(size_t)NH * SQ * HD + 8192];
__device__ __half g_vh[(size_t)NH * SQ * HD + 8192];

// ============================ PTX helpers ====================================
__device__ __forceinline__ uint32_t smem_u32(const void* p) {
    uint32_t a;
    asm("{ .reg .u64 t; cvta.to.shared.u64 t, %1; cvt.u32.u64 %0, t; }"
        : "=r"(a) : "l"(p));
    return a;
}
__device__ __forceinline__ void cp16(uint32_t dst, const void* src) {
    asm volatile("cp.async.cg.shared.global [%0], [%1], 16;" :: "r"(dst), "l"(src));
}
#define CP_COMMIT() asm volatile("cp.async.commit_group;" ::: "memory")
#define CP_WAIT(n)  asm volatile("cp.async.wait_group %0;" :: "n"(n) : "memory")

__device__ __forceinline__ void ldm_x4(uint32_t* r, uint32_t a) {
    asm volatile("ldmatrix.sync.aligned.m8n8.x4.shared.b16 {%0,%1,%2,%3}, [%4];"
        : "=r"(r[0]), "=r"(r[1]), "=r"(r[2]), "=r"(r[3]) : "r"(a));
}
__device__ __forceinline__ void ldm_x4t(uint32_t* r, uint32_t a) {
    asm volatile("ldmatrix.sync.aligned.m8n8.x4.trans.shared.b16 {%0,%1,%2,%3}, [%4];"
        : "=r"(r[0]), "=r"(r[1]), "=r"(r[2]), "=r"(r[3]) : "r"(a));
}
// fp32-accum HMMA
__device__ __forceinline__ void mma16816(float* c, const uint32_t* a, const uint32_t* b) {
    asm volatile("mma.sync.aligned.m16n8k16.row.col.f32.f16.f16.f32 "
        "{%0,%1,%2,%3}, {%4,%5,%6,%7}, {%8,%9}, {%0,%1,%2,%3};"
        : "+f"(c[0]), "+f"(c[1]), "+f"(c[2]), "+f"(c[3])
        : "r"(a[0]), "r"(a[1]), "r"(a[2]), "r"(a[3]), "r"(b[0]), "r"(b[1]));
}
// fp16-accum HMMA (C = 2 packed half2 regs; layout == PV A-fragment layout)
__device__ __forceinline__ void mma16816h(uint32_t* c, const uint32_t* a, const uint32_t* b) {
    asm volatile("mma.sync.aligned.m16n8k16.row.col.f16.f16.f16.f16 "
        "{%0,%1}, {%2,%3,%4,%5}, {%6,%7}, {%0,%1};"
        : "+r"(c[0]), "+r"(c[1])
        : "r"(a[0]), "r"(a[1]), "r"(a[2]), "r"(a[3]), "r"(b[0]), "r"(b[1]));
}
#define SW128(o) ((o) ^ (((o) >> 3) & 0x70))

// ============================================================================
// fused pack fp32 -> fp16 for three tensors (vectorized x4)
// ============================================================================
__global__ void pack3_kernel(const float4* __restrict__ s0, uint2* __restrict__ d0, size_t n0,
                             const float4* __restrict__ s1, uint2* __restrict__ d1, size_t n1,
                             const float4* __restrict__ s2, uint2* __restrict__ d2, size_t n2)
{
    const size_t total = n0 + n1 + n2;
    for (size_t i = blockIdx.x * (size_t)blockDim.x + threadIdx.x; i < total;
         i += (size_t)gridDim.x * blockDim.x) {
        const float4* s; uint2* d; size_t k;
        if (i < n0)           { s = s0; d = d0; k = i; }
        else if (i < n0 + n1) { s = s1; d = d1; k = i - n0; }
        else                  { s = s2; d = d2; k = i - n0 - n1; }
        float4 v = s[k];
        __half2 lo; lo.x = __float2half_rn(v.x); lo.y = __float2half_rn(v.y);
        __half2 hi; hi.x = __float2half_rn(v.z); hi.y = __float2half_rn(v.w);
        uint2 o; o.x = *(uint32_t*)&lo; o.y = *(uint32_t*)&hi;
        d[k] = o;
    }
}

// ============================================================================
// HGEMM NT: C[M,N] = A[M,K]@B[N,K]^T + bias (+resid). OutT = float or __half.
// 128x128 CTA, 8 warps (64x32/warp), KC=64, SW128, 3-stage cp.async.
// ============================================================================
#define HG_STAGE 32768
#define HG_SMEM  (3 * HG_STAGE)   // 98304
#define NCH (GK / 64)             // 20

template <typename OutT, bool RESID>
__global__ __launch_bounds__(256)
void hgemm_nt_kernel(OutT* __restrict__ C,
                     const __half* __restrict__ A,
                     const __half* __restrict__ B,
                     const float* __restrict__ bias,
                     const float* __restrict__ Rz,
                     int M, int N)
{
    extern __shared__ char smem[];
    const uint32_t sb = smem_u32(smem);
    const int tid = threadIdx.x, lane = tid & 31, wid = tid >> 5;
    const int wm = wid >> 2, wn = wid & 3;
    const int m0 = blockIdx.y * 128, n0 = blockIdx.x * 128;

    float c[4][4][4];
#pragma unroll
    for (int i = 0; i < 4; i++)
#pragma unroll
        for (int j = 0; j < 4; j++)
#pragma unroll
            for (int r = 0; r < 4; r++) c[i][j][r] = 0.f;

    auto issue = [&](int st, int kk) {
        const uint32_t Ab = sb + st * HG_STAGE;
#pragma unroll
        for (int i = 0; i < 4; i++) {
            int lin = tid + i * 256;
            int r = lin >> 3, seg = lin & 7;
            cp16(Ab + SW128((uint32_t)(r * 128 + seg * 16)),
                 A + (size_t)(m0 + r) * GK + kk + seg * 8);
        }
#pragma unroll
        for (int i = 0; i < 4; i++) {
            int lin = tid + i * 256;
            int r = lin >> 3, seg = lin & 7;
            cp16(Ab + 16384 + SW128((uint32_t)(r * 128 + seg * 16)),
                 B + (size_t)(n0 + r) * GK + kk + seg * 8);
        }
        CP_COMMIT();
    };

    issue(0, 0);
    issue(1, 64);
    for (int ch = 0; ch < NCH; ch++) {
        if (ch + 2 < NCH) { issue((ch + 2) % 3, (ch + 2) * 64); CP_WAIT(2); }
        else if (ch + 1 < NCH) { CP_WAIT(1); }
        else { CP_WAIT(0); }
        __syncthreads();

        const uint32_t Ab = sb + (ch % 3) * HG_STAGE;
        const uint32_t Bb = Ab + 16384;
#pragma unroll
        for (int ks = 0; ks < 4; ks++) {
            const int kk = ks * 16;
            uint32_t a[4][4];
#pragma unroll
            for (int i = 0; i < 4; i++) {
                int row = wm * 64 + i * 16 + (lane & 7) + ((lane >> 3) & 1) * 8;
                int ko  = kk + (lane >> 4) * 8;
                ldm_x4(a[i], Ab + SW128((uint32_t)(row * 128 + ko * 2)));
            }
#pragma unroll
            for (int j = 0; j < 2; j++) {
                uint32_t b4[4];
                int rowb = wn * 32 + j * 16 + (lane & 7) + (lane >> 4) * 8;
                int kob  = kk + ((lane >> 3) & 1) * 8;
                ldm_x4(b4, Bb + SW128((uint32_t)(rowb * 128 + kob * 2)));
#pragma unroll
                for (int i = 0; i < 4; i++) {
                    mma16816(c[i][2 * j],     a[i], b4);
                    mma16816(c[i][2 * j + 1], a[i], b4 + 2);
                }
            }
        }
        __syncthreads();
    }

    // epilogue
#pragma unroll
    for (int i = 0; i < 4; i++) {
        const int row = m0 + wm * 64 + i * 16 + (lane >> 2);
#pragma unroll
        for (int j = 0; j < 4; j++) {
            const int col = n0 + wn * 32 + j * 8 + (lane & 3) * 2;
            const float2 bv = *(const float2*)&bias[col];
#pragma unroll
            for (int h = 0; h < 2; h++) {
                const int rr = row + h * 8;
                if (rr >= M) continue;
                float ox = c[i][j][2 * h]     + bv.x;
                float oy = c[i][j][2 * h + 1] + bv.y;
                if (RESID) {
                    float2 rv = *(const float2*)&Rz[(size_t)rr * N + col];
                    ox += rv.x; oy += rv.y;
                }
                if (sizeof(OutT) == 2) {
                    __half2 hv; hv.x = __float2half_rn(ox); hv.y = __float2half_rn(oy);
                    *(__half2*)&((__half*)C)[(size_t)rr * N + col] = hv;
                } else {
                    *(float2*)&((float*)C)[(size_t)rr * N + col] = make_float2(ox, oy);
                }
            }
        }
    }
}

// ============================================================================
// RoPE + split, vectorized: cos/sin tables satisfy cos[d+40]==cos[d], so each
// thread handles the (d, d+40) pair for 2 consecutive d with one cos/sin load.
// q pre-scaled by SCALE*log2(e).
// ============================================================================
__global__ void rope_split_kernel(const float* __restrict__ cosb,
                                  const float* __restrict__ sinb)
{
    const int s = blockIdx.x;
    const __half2* row = (const __half2*)(g_qkvh + (size_t)s * HID3);
    for (int it = threadIdx.x; it < NH * 20; it += blockDim.x) {
        const int h = it / 20, dp = it - h * 20;    // dp: half2 index within [0,40)
        const int d = dp * 2;
        const float2 c2 = *(const float2*)&cosb[s * HD + d];
        const float2 s2 = *(const float2*)&sinb[s * HD + d];
        const int base = h * 40;                    // half2 units within 640-wide row

        __half2 qlo = row[base + dp],        qhi = row[base + 20 + dp];
        __half2 klo = row[640 + base + dp],  khi = row[640 + base + 20 + dp];
        __half2 vlo = row[1280 + base + dp], vhi = row[1280 + base + 20 + dp];

        float2 ql = __half22float2(qlo), qh2 = __half22float2(qhi);
        float2 kl = __half22float2(klo), kh2 = __half22float2(khi);

        __half2 qo_lo, qo_hi, ko_lo, ko_hi;
        qo_lo.x = __float2half_rn((ql.x * c2.x - qh2.x * s2.x) * SCALE_LOG2);
        qo_lo.y = __float2half_rn((ql.y * c2.y - qh2.y * s2.y) * SCALE_LOG2);
        qo_hi.x = __float2half_rn((qh2.x * c2.x + ql.x * s2.x) * SCALE_LOG2);
        qo_hi.y = __float2half_rn((qh2.y * c2.y + ql.y * s2.y) * SCALE_LOG2);
        ko_lo.x = __float2half_rn(kl.x * c2.x - kh2.x * s2.x);
        ko_lo.y = __float2half_rn(kl.y * c2.y - kh2.y * s2.y);
        ko_hi.x = __float2half_rn(kh2.x * c2.x + kl.x * s2.x);
        ko_hi.y = __float2half_rn(kh2.y * c2.y + kl.y * s2.y);

        const size_t ob = ((size_t)h * SQ + s) * HD + d;   // element index (even)
        *(__half2*)&g_qh[ob]      = qo_lo;
        *(__half2*)&g_qh[ob + 40] = qo_hi;
        *(__half2*)&g_kh[ob]      = ko_lo;
        *(__half2*)&g_kh[ob + 40] = ko_hi;
        *(__half2*)&g_vh[ob]      = vlo;
        *(__half2*)&g_vh[ob + 40] = vhi;
    }
}

// ============================================================================
// Flash attention (best-measured R14 config): 4 warps x m32, Q frags hoisted
// to registers, fp16-accum QK^T whose C-frags ARE the PV A-frags (exp2
// in-register), 2-stage KV double-buffer with trailing prefetch.
// grid (25, 16), 128 threads, 3 CTAs/SM.
// ============================================================================
#define FK_BYTES 11264          // 64 * 176
#define FSTAGE   22528          // K + V
#define F_SMEM   (2 * FSTAGE)   // 45056
#define NKT      (SQ / 64)      // 49

__global__ __launch_bounds__(128, 3)
void flash_mma_kernel()
{
    extern __shared__ char smem[];
    const uint32_t sb = smem_u32(smem);
    const int tid = threadIdx.x, lane = tid & 31, wid = tid >> 5;
    const int hh = blockIdx.y, q0 = blockIdx.x * 128;
    const __half* qh = g_qh + (size_t)hh * SQ * HD;
    const __half* kh = g_kh + (size_t)hh * SQ * HD;
    const __half* vh = g_vh + (size_t)hh * SQ * HD;

    auto issue_kv = [&](int buf, int kbase) {
        const uint32_t Kb = sb + buf * FSTAGE;
#pragma unroll
        for (int i = 0; i < 10; i++) {
            int lin = tid + i * 128;
            if (lin < 640) {
                int r = lin / 10, seg = lin % 10;
                cp16(Kb + (uint32_t)(r * 176 + seg * 16),
                     kh + (size_t)(kbase + r) * HD + seg * 8);
            } else {
                int l2 = lin - 640;
                int r = l2 / 10, seg = l2 % 10;
                cp16(Kb + FK_BYTES + (uint32_t)(r * 176 + seg * 16),
                     vh + (size_t)(kbase + r) * HD + seg * 8);
            }
        }
        CP_COMMIT();
    };

    // ---- load Q tile (128 rows x 176B) into stage area, hoist frags ----
#pragma unroll
    for (int i = 0; i < 10; i++) {
        int lin = tid + i * 128;
        int r = lin / 10, seg = lin % 10;
        cp16(sb + (uint32_t)(r * 176 + seg * 16),
             qh + (size_t)(q0 + r) * HD + seg * 8);
    }
    CP_COMMIT();
    CP_WAIT(0);
    __syncthreads();

    uint32_t qf[2][5][4];   // [row-half][k-step][frag]
#pragma unroll
    for (int h = 0; h < 2; h++)
#pragma unroll
        for (int ks = 0; ks < 5; ks++) {
            int row = wid * 32 + h * 16 + (lane & 7) + ((lane >> 3) & 1) * 8;
            int ko  = ks * 16 + (lane >> 4) * 8;
            ldm_x4(qf[h][ks], sb + (uint32_t)(row * 176 + ko * 2));
        }
    __syncthreads();   // all warps done reading Q region before KV overwrites

    issue_kv(0, 0);
    issue_kv(1, 64);

    float o[2][10][4];
#pragma unroll
    for (int h = 0; h < 2; h++)
#pragma unroll
        for (int d = 0; d < 10; d++)
#pragma unroll
            for (int r = 0; r < 4; r++) o[h][d][r] = 0.f;
    float l[2][2] = {{0.f, 0.f}, {0.f, 0.f}};
    const __half2 clampv = __floats2half2_rn(11.f, 11.f);   // p <= 2048

    for (int kt = 0; kt < NKT; kt++) {
        if (kt < NKT - 1) { CP_WAIT(1); } else { CP_WAIT(0); }
        __syncthreads();

        const uint32_t Kb = sb + (kt & 1) * FSTAGE;
        const uint32_t Vb = Kb + FK_BYTES;

        // S = Q @ K^T  (32 x 64 per warp, fp16 accum, exp2 domain)
        uint32_t c[2][8][2];
#pragma unroll
        for (int h = 0; h < 2; h++)
#pragma unroll
            for (int j = 0; j < 8; j++) { c[h][j][0] = 0u; c[h][j][1] = 0u; }

#pragma unroll
        for (int ks = 0; ks < 5; ks++) {
#pragma unroll
            for (int j = 0; j < 4; j++) {
                uint32_t b4[4];
                int rowb = j * 16 + (lane & 7) + (lane >> 4) * 8;
                int kob  = ks * 16 + ((lane >> 3) & 1) * 8;
                ldm_x4(b4, Kb + (uint32_t)(rowb * 176 + kob * 2));
#pragma unroll
                for (int h = 0; h < 2; h++) {
                    mma16816h(c[h][2 * j],     qf[h][ks], b4);
                    mma16816h(c[h][2 * j + 1], qf[h][ks], b4 + 2);
                }
            }
        }

        // p = 2^s in place (C-frags become PV A-frags); accumulate l
#pragma unroll
        for (int h = 0; h < 2; h++) {
            __half2 acc0 = __floats2half2_rn(0.f, 0.f);
            __half2 acc1 = acc0;
#pragma unroll
            for (int j = 0; j < 8; j++) {
                __half2 v0 = h2exp2(__hmin2(*(__half2*)&c[h][j][0], clampv));
                __half2 v1 = h2exp2(__hmin2(*(__half2*)&c[h][j][1], clampv));
                c[h][j][0] = *(uint32_t*)&v0;
                c[h][j][1] = *(uint32_t*)&v1;
                acc0 = __hadd2(acc0, v0);
                acc1 = __hadd2(acc1, v1);
            }
            float2 f0 = __half22float2(acc0), f1 = __half22float2(acc1);
            l[h][0] += f0.x + f0.y;
            l[h][1] += f1.x + f1.y;
        }

        // O += P @ V
#pragma unroll
        for (int jj = 0; jj < 4; jj++) {
#pragma unroll
            for (int d2 = 0; d2 < 5; d2++) {
                uint32_t b4[4];
                int rowv = jj * 16 + (lane & 7) + ((lane >> 3) & 1) * 8;
                int c16  = d2 * 2 + (lane >> 4);
                ldm_x4t(b4, Vb + (uint32_t)(rowv * 176 + c16 * 16));
#pragma unroll
                for (int h = 0; h < 2; h++) {
                    uint32_t ap[4] = {c[h][2 * jj][0], c[h][2 * jj][1],
                                      c[h][2 * jj + 1][0], c[h][2 * jj + 1][1]};
                    mma16816(o[h][2 * d2],     ap, b4);
                    mma16816(o[h][2 * d2 + 1], ap, b4 + 2);
                }
            }
        }
        __syncthreads();
        if (kt + 2 < NKT) issue_kv(kt & 1, (kt + 2) * 64);
    }

    // reduce l across the 4 lanes of each row quad
#pragma unroll
    for (int h = 0; h < 2; h++)
#pragma unroll
        for (int g = 0; g < 2; g++) {
            l[h][g] += __shfl_xor_sync(0xffffffffu, l[h][g], 1);
            l[h][g] += __shfl_xor_sync(0xffffffffu, l[h][g], 2);
        }

    // write attn fp16 (rows >= SQ land in ga_h padding rows; ignored by proj)
#pragma unroll
    for (int h = 0; h < 2; h++) {
        const float il0 = 1.f / l[h][0], il1 = 1.f / l[h][1];
        const int r0 = q0 + wid * 32 + h * 16 + (lane >> 2);
#pragma unroll
        for (int d = 0; d < 10; d++) {
            const int col = hh * HD + d * 8 + (lane & 3) * 2;
            __half2 h0; h0.x = __float2half_rn(o[h][d][0] * il0);
                        h0.y = __float2half_rn(o[h][d][1] * il0);
            *(__half2*)&ga_h[(size_t)r0 * GK + col] = h0;
            __half2 h1; h1.x = __float2half_rn(o[h][d][2] * il1);
                        h1.y = __float2half_rn(o[h][d][3] * il1);
            *(__half2*)&ga_h[(size_t)(r0 + 8) * GK + col] = h1;
        }
    }
}

// ============================================================================
// launch
// ============================================================================
extern "C" void kernel_launch(void* const* d_in, const int* in_sizes, int n_in,
                              void* d_out, int out_size)
{
    const float* hidden  = (const float*)d_in[0];
    const float* x_norm  = (const float*)d_in[1];
    const float* qkv_w   = (const float*)d_in[2];
    const float* qkv_b   = (const float*)d_in[3];
    const float* proj_w  = (const float*)d_in[4];
    const float* proj_b  = (const float*)d_in[5];
    const float* cosb    = (const float*)d_in[6];
    const float* sinb    = (const float*)d_in[7];
    float* out = (float*)d_out;

    __half *qkvh, *xh, *w1h, *w2h, *ah;
    cudaGetSymbolAddress((void**)&qkvh, g_qkvh);
    cudaGetSymbolAddress((void**)&xh,  gx_h);
    cudaGetSymbolAddress((void**)&w1h, gw1_h);
    cudaGetSymbolAddress((void**)&w2h, gw2_h);
    cudaGetSymbolAddress((void**)&ah,  ga_h);

    cudaFuncSetAttribute(hgemm_nt_kernel<__half, false>,
                         cudaFuncAttributeMaxDynamicSharedMemorySize, HG_SMEM);
    cudaFuncSetAttribute(hgemm_nt_kernel<float, true>,
                         cudaFuncAttributeMaxDynamicSharedMemorySize, HG_SMEM);
    cudaFuncSetAttribute(flash_mma_kernel,
                         cudaFuncAttributeMaxDynamicSharedMemorySize, F_SMEM);

    // 0. pack all three fp32 inputs to fp16 (one fused kernel, float4 lanes)
    pack3_kernel<<<1184, 256>>>(
        (const float4*)x_norm, (uint2*)xh,  (size_t)SQ * GK / 4,
        (const float4*)qkv_w,  (uint2*)w1h, (size_t)HID3 * GK / 4,
        (const float4*)proj_w, (uint2*)w2h, (size_t)HID * GK / 4);

    // 1. qkv = x_norm @ qkv_w^T + qkv_b (fp16 out)
    {
        dim3 grid(HID3 / 128, MPAD / 128);
        hgemm_nt_kernel<__half, false><<<grid, 256, HG_SMEM>>>(
            qkvh, xh, w1h, qkv_b, nullptr, SQ, HID3);
    }
    // 2. rope + split to fp16 [H,S,D] (q pre-scaled into exp2 domain)
    rope_split_kernel<<<SQ, 256>>>(cosb, sinb);

    // 3. flash attention (R14 best-measured config)
    {
        dim3 grid((SQ + 127) / 128, NH);
        flash_mma_kernel<<<grid, 128, F_SMEM>>>();
    }
    // 4. out = hidden + attn @ proj_w^T + proj_b
    {
        dim3 grid(HID / 128, MPAD / 128);
        hgemm_nt_kernel<float, true><<<grid, 256, HG_SMEM>>>(
            out, ah, w2h, proj_b, hidden, SQ, HID);
    }
}